// round 16
// baseline (speedup 1.0000x reference)
#include <cuda_runtime.h>
#include <cuda_bf16.h>
#include <cstdint>

// Shapes fixed by reference setup_inputs():
//   z_e: (B=64, D=64, H=32, W=32) fp32, embedding: (K=1024, D=64) fp32
// Output layout (fp32 concat):
//   [0, 4194304)   z_q (B,D,H,W)
//   [4194304]      commitment_loss
//   [4194305,...)  indices (B,H,W) as float (65536)
//   [4259841]      codebook_usage

#define NVEC   65536
#define DDIM   64
#define KCODES 1024
#define ZQ_ELEMS 4194304
#define LOSS_OFF 4194304
#define IDX_OFF  4194305
#define USAGE_OFF 4259841

#define TAU 0.4f
#define NBLOCKS 256

// ---- dynamic smem byte offsets ----
#define AHI_OFF   0        // A hi fragments: 16 tiles x 2KB           32KB
#define BUF0_OFF  32768    // B chunk buffer 0 (64 codes hi)            8KB
#define BUF1_OFF  40960    // B chunk buffer 1                          8KB  (BUF0+BUF1 = X staging)
#define CS_OFF    49152    // 1024 x float half-norms                   4KB
#define SIDX_OFF  53248    // 256 x int
#define SFB_OFF   54272    // 256 x int flags
#define SMASK_OFF 55296    // 8 x uint ballot masks
#define XROW_OFF  55328    // 64 x float refinement row
#define WV_OFF    55584    // 8 x float
#define WI_OFF    55616    // 8 x int
#define RED_OFF   55648    // 256 x float
#define SOLD_OFF  56672    // uint
#define SMEM_BYTES 56832

// ---- scratch (no device allocation allowed) ----
__device__ float        g_chalf[KCODES];        // 0.5*||e_k||^2
__device__ unsigned int g_bh[16 * 2048];        // B hi image: 16 chunks x 8KB
__device__ int          g_used[KCODES];
__device__ float        g_partial[NBLOCKS];
__device__ unsigned int g_done_ctr;

__device__ __forceinline__ uint32_t smem_u32(const void* p) {
    uint32_t a;
    asm("{ .reg .u64 t; cvta.to.shared.u64 t, %1; cvt.u32.u64 %0, t; }" : "=r"(a) : "l"(p));
    return a;
}

#define CP_ASYNC16(dst, src) \
    asm volatile("cp.async.cg.shared.global [%0], [%1], 16;" :: "r"(dst), "l"(src))
#define CP_COMMIT() asm volatile("cp.async.commit_group;" ::: "memory")
#define CP_WAIT1()  asm volatile("cp.async.wait_group 1;" ::: "memory")
#define CP_WAIT0()  asm volatile("cp.async.wait_group 0;" ::: "memory")

__device__ __forceinline__ void mma16816(float* d, const uint4 a, const uint2 b) {
    asm volatile(
        "mma.sync.aligned.m16n8k16.row.col.f32.bf16.bf16.f32 "
        "{%0,%1,%2,%3}, {%4,%5,%6,%7}, {%8,%9}, {%0,%1,%2,%3};"
        : "+f"(d[0]), "+f"(d[1]), "+f"(d[2]), "+f"(d[3])
        : "r"(a.x), "r"(a.y), "r"(a.z), "r"(a.w), "r"(b.x), "r"(b.y));
}

// ---------------------------------------------------------------------------
// Kernel A: half-norms + hi-only fragment image of B. <<<8,128>>>
// Image: chunk=k/64 (8KB each). For (chunk, ks, code c=k%64, p, w):
//   offset = chunk*8192 + ks*2048 + c*32 + p*8 + w*4
// where dim-pair d2 = ks*8 + pr, p = pr&3, w = (pr&4)>>2.
// 32 lanes (8 codes x 4 p) of a group read one contiguous 256B span.
// ---------------------------------------------------------------------------
__global__ void vq_prep(const float* __restrict__ emb) {
    int t = blockIdx.x * 128 + threadIdx.x;   // code id 0..1023
    const float* ep = emb + (size_t)t * DDIM;
    char* bimg = (char*)g_bh + (t >> 6) * 8192;
    int c = t & 63;
    float s = 0.f;
#pragma unroll
    for (int d2 = 0; d2 < 32; d2++) {
        float x0 = ep[2 * d2], x1 = ep[2 * d2 + 1];
        s = fmaf(x0, x0, s);
        s = fmaf(x1, x1, s);
        unsigned uh = (unsigned)__bfloat16_as_ushort(__float2bfloat16(x0)) |
                      ((unsigned)__bfloat16_as_ushort(__float2bfloat16(x1)) << 16);
        int ks = d2 >> 3, pr = d2 & 7;
        *(unsigned*)(bimg + ks * 2048 + c * 32 + (pr & 3) * 8 + ((pr & 4) >> 2) * 4) = uh;
    }
    g_chalf[t] = 0.5f * s;
    g_used[t] = 0;
    if (t == 0) g_done_ctr = 0u;
}

// ---------------------------------------------------------------------------
// Kernel B: single-split bf16 HMMA distance GEMM + top-2 argmax + exact
// refinement + epilogue. grid = 256 blocks (256 vectors), 256 threads.
// 64 MMAs / chunk / warp (3x fewer than R14) — HMMA issue-rate bound.
// ---------------------------------------------------------------------------
__global__ void __launch_bounds__(256, 2)
vq_main(const float* __restrict__ ze, const float* __restrict__ emb,
        float* __restrict__ out) {
    extern __shared__ char sm[];
    const uint32_t sbase = smem_u32(sm);
    const int tid = threadIdx.x;
    const int wid = tid >> 5;
    const int lid = tid & 31;
    const int g   = lid >> 2;
    const int p   = lid & 3;
    const int n0  = blockIdx.x * 256;
    const int b   = n0 >> 10;
    const int hw0 = n0 & 1023;
    const size_t zbase = (size_t)b * 65536 + hw0;

    float*    csp    = (float*)(sm + CS_OFF);
    int*      sidx   = (int*)(sm + SIDX_OFF);
    int*      sflagb = (int*)(sm + SFB_OFF);
    unsigned* smask  = (unsigned*)(sm + SMASK_OFF);
    float*    xrow   = (float*)(sm + XROW_OFF);
    float*    wv     = (float*)(sm + WV_OFF);
    int*      wi     = (int*)(sm + WI_OFF);
    float*    red    = (float*)(sm + RED_OFF);
    unsigned* sold   = (unsigned*)(sm + SOLD_OFF);

    // ---- half-norms into smem ----
#pragma unroll
    for (int i = 0; i < 4; i++) csp[tid + i * 256] = g_chalf[tid + i * 256];

    // ---- convert X into A hi fragments: 4 passes of 16 dims (ks=h) ----
    // Staging buffer = BUF0..BUF1 (16KB contiguous).
#pragma unroll
    for (int h = 0; h < 4; h++) {
        float4* Xs4 = (float4*)(sm + BUF0_OFF);   // [16 dims][64 float4]
#pragma unroll
        for (int i = 0; i < 4; i++) {
            int q = tid + i * 256;
            int d = q >> 6, c4 = q & 63;
            Xs4[d * 64 + c4] =
                ((const float4*)(ze + zbase + (size_t)(h * 16 + d) * 1024))[c4];
        }
        __syncthreads();
        const float* Xs = (const float*)(sm + BUF0_OFF);
        const int row = tid;
        const int tile = row >> 4, r16 = row & 15;
        const int gg = r16 & 7, hi8 = r16 >> 3;
#pragma unroll
        for (int j = 0; j < 8; j++) {           // d2 = h*8 + j
            float x0 = Xs[(2 * j) * 256 + row];
            float x1 = Xs[(2 * j + 1) * 256 + row];
            unsigned uh = (unsigned)__bfloat16_as_ushort(__float2bfloat16(x0)) |
                          ((unsigned)__bfloat16_as_ushort(__float2bfloat16(x1)) << 16);
            int slot = hi8 + ((j & 4) >> 1);
            int off = tile * 2048 + (h * 32 + gg * 4 + (j & 3)) * 16 + slot * 4;
            *(unsigned*)(sm + AHI_OFF + off) = uh;
        }
        __syncthreads();
    }

    // ---- prefetch B chunk 0 into BUF0 ----
    {
        const uint4* src = (const uint4*)g_bh;
#pragma unroll
        for (int j = 0; j < 2; j++)
            CP_ASYNC16(sbase + BUF0_OFF + (tid + j * 256) * 16, src + tid + j * 256);
        CP_COMMIT();
    }

    // ---- main loop: 16 chunks of 64 codes, double-buffered via cp.async ----
    float v[4], sec[4];
    int   ix[4];
#pragma unroll
    for (int i = 0; i < 4; i++) { v[i] = -3.4e38f; sec[i] = -3.4e38f; ix[i] = 0; }

    const int t0base = AHI_OFF + (wid * 2) * 2048;
    const int t1base = t0base + 2048;

    for (int chunk = 0; chunk < 16; chunk++) {
        if (chunk < 15) {
            const uint4* src = (const uint4*)g_bh + (chunk + 1) * 512;
            uint32_t dst = sbase + (((chunk + 1) & 1) ? BUF1_OFF : BUF0_OFF);
#pragma unroll
            for (int j = 0; j < 2; j++)
                CP_ASYNC16(dst + (tid + j * 256) * 16, src + tid + j * 256);
            CP_COMMIT();
            CP_WAIT1();
        } else {
            CP_WAIT0();
        }
        __syncthreads();

        const char* bbuf = sm + ((chunk & 1) ? BUF1_OFF : BUF0_OFF);

        // two half-passes of 4 nt each -> 32 live accumulators
#pragma unroll
        for (int h2 = 0; h2 < 2; h2++) {
            float acc[8][4];   // [ntl] tile0, [4+ntl] tile1
#pragma unroll
            for (int q = 0; q < 8; q++)
#pragma unroll
                for (int j = 0; j < 4; j++) acc[q][j] = 0.f;

#pragma unroll
            for (int ks = 0; ks < 4; ks++) {
                uint4 ah0 = *(const uint4*)(sm + t0base + (ks * 32 + lid) * 16);
                uint4 ah1 = *(const uint4*)(sm + t1base + (ks * 32 + lid) * 16);
#pragma unroll
                for (int ntl = 0; ntl < 4; ntl++) {
                    int c = (h2 * 4 + ntl) * 8 + g;
                    uint2 bf = *(const uint2*)(bbuf + ks * 2048 + c * 32 + p * 8);
                    mma16816(acc[ntl],     ah0, bf);
                    mma16816(acc[4 + ntl], ah1, bf);
                }
            }

            // fold this half: s = dot - 0.5||e||^2
#pragma unroll
            for (int ntl = 0; ntl < 4; ntl++) {
                int kk = chunk * 64 + (h2 * 4 + ntl) * 8 + 2 * p;
                float2 ch = *(const float2*)(csp + kk);
                float s0 = acc[ntl][0] - ch.x, s1 = acc[ntl][1] - ch.y;
                float s2 = acc[ntl][2] - ch.x, s3 = acc[ntl][3] - ch.y;
                float s4 = acc[4 + ntl][0] - ch.x, s5 = acc[4 + ntl][1] - ch.y;
                float s6 = acc[4 + ntl][2] - ch.x, s7 = acc[4 + ntl][3] - ch.y;
                if (s0 > v[0]) { sec[0] = v[0]; v[0] = s0; ix[0] = kk; }     else sec[0] = fmaxf(sec[0], s0);
                if (s1 > v[0]) { sec[0] = v[0]; v[0] = s1; ix[0] = kk + 1; } else sec[0] = fmaxf(sec[0], s1);
                if (s2 > v[1]) { sec[1] = v[1]; v[1] = s2; ix[1] = kk; }     else sec[1] = fmaxf(sec[1], s2);
                if (s3 > v[1]) { sec[1] = v[1]; v[1] = s3; ix[1] = kk + 1; } else sec[1] = fmaxf(sec[1], s3);
                if (s4 > v[2]) { sec[2] = v[2]; v[2] = s4; ix[2] = kk; }     else sec[2] = fmaxf(sec[2], s4);
                if (s5 > v[2]) { sec[2] = v[2]; v[2] = s5; ix[2] = kk + 1; } else sec[2] = fmaxf(sec[2], s5);
                if (s6 > v[3]) { sec[3] = v[3]; v[3] = s6; ix[3] = kk; }     else sec[3] = fmaxf(sec[3], s6);
                if (s7 > v[3]) { sec[3] = v[3]; v[3] = s7; ix[3] = kk + 1; } else sec[3] = fmaxf(sec[3], s7);
            }
        }
        __syncthreads();
    }

    // ---- top-2 merge across the 4 lanes (p) sharing each row ----
#pragma unroll
    for (int i = 0; i < 4; i++) {
#pragma unroll
        for (int off = 1; off <= 2; off <<= 1) {
            float ov = __shfl_xor_sync(0xffffffffu, v[i], off);
            int   oi = __shfl_xor_sync(0xffffffffu, ix[i], off);
            float os = __shfl_xor_sync(0xffffffffu, sec[i], off);
            float mn = fminf(v[i], ov);
            sec[i] = fmaxf(mn, fmaxf(sec[i], os));
            ix[i] = (ov > v[i]) ? oi : ((ov < v[i]) ? ix[i] : min(ix[i], oi));
            v[i] = fmaxf(v[i], ov);
        }
    }
    if (p == 0) {
        int rows[4] = { wid * 32 + g, wid * 32 + 8 + g,
                        wid * 32 + 16 + g, wid * 32 + 24 + g };
#pragma unroll
        for (int i = 0; i < 4; i++) {
            sidx[rows[i]]   = ix[i];
            sflagb[rows[i]] = (v[i] - sec[i] < TAU) ? 1 : 0;
        }
    }
    __syncthreads();

    // ---- ballot masks (8 warps x 32 rows) ----
    {
        unsigned bm = __ballot_sync(0xffffffffu, sflagb[tid] != 0);
        if (lid == 0) smask[wid] = bm;
    }
    __syncthreads();

    // ---- exact fp32 refinement for flagged rows (~6%) ----
    for (int w = 0; w < 8; w++) {
        unsigned m = smask[w];
        while (m) {
            int nl = w * 32 + (__ffs(m) - 1);
            m &= m - 1;
            if (tid < 64) xrow[tid] = ze[zbase + (size_t)tid * 1024 + nl];
            __syncthreads();
            float bl = -3.4e38f; int bi = 0;
#pragma unroll
            for (int j = 0; j < 4; j++) {
                int k = tid * 4 + j;
                const float4* er = (const float4*)(emb + (size_t)k * DDIM);
                float dot = 0.f;
#pragma unroll
                for (int q4 = 0; q4 < 16; q4++) {
                    float4 ev = er[q4];
                    float4 xv = *(const float4*)&xrow[q4 * 4];
                    dot = fmaf(xv.x, ev.x, dot);
                    dot = fmaf(xv.y, ev.y, dot);
                    dot = fmaf(xv.z, ev.z, dot);
                    dot = fmaf(xv.w, ev.w, dot);
                }
                float s = dot - csp[k];
                if (s > bl) { bl = s; bi = k; }
            }
#pragma unroll
            for (int off = 16; off; off >>= 1) {
                float ov = __shfl_xor_sync(0xffffffffu, bl, off);
                int   oi = __shfl_xor_sync(0xffffffffu, bi, off);
                if (ov > bl || (ov == bl && oi < bi)) { bl = ov; bi = oi; }
            }
            if (lid == 0) { wv[wid] = bl; wi[wid] = bi; }
            __syncthreads();
            if (tid == 0) {
                float fb = wv[0]; int fi = wi[0];
#pragma unroll
                for (int ww = 1; ww < 8; ww++)
                    if (wv[ww] > fb || (wv[ww] == fb && wi[ww] < fi)) { fb = wv[ww]; fi = wi[ww]; }
                sidx[nl] = fi;
            }
            __syncthreads();
        }
    }

    // ---- epilogue: per-thread row. indices, usage, z_q, loss partial ----
    {
        const int k = sidx[tid];
        out[IDX_OFF + n0 + tid] = (float)k;
        g_used[k] = 1;
        const float* ep = emb + (size_t)k * DDIM;
        float lsum = 0.f;
#pragma unroll
        for (int d = 0; d < DDIM; d++) {
            float e = __ldg(ep + d);                       // 256KB codebook: L1/L2 hit
            float x = ze[zbase + (size_t)d * 1024 + tid];  // coalesced across lanes
            float df = x - e;
            lsum = fmaf(df, df, lsum);
            out[zbase + (size_t)d * 1024 + tid] = e;       // coalesced
        }
        red[tid] = lsum;
    }
    __syncthreads();
#pragma unroll
    for (int s = 128; s; s >>= 1) {
        if (tid < s) red[tid] += red[tid + s];
        __syncthreads();
    }
    if (tid == 0) g_partial[blockIdx.x] = red[0];

    // ---- last-block final reductions ----
    __threadfence();
    __syncthreads();
    if (tid == 0) *sold = atomicAdd(&g_done_ctr, 1u);
    __syncthreads();
    if (*sold == NBLOCKS - 1) {
        __threadfence();
        volatile float* gp = g_partial;
        volatile int*   gu = g_used;
        float ls = gp[tid];
        int us = 0;
#pragma unroll
        for (int j = 0; j < 4; j++) us += gu[tid * 4 + j];
        int* redi = (int*)(sm + SFB_OFF);
        red[tid]  = ls;
        redi[tid] = us;
        __syncthreads();
#pragma unroll
        for (int s = 128; s; s >>= 1) {
            if (tid < s) { red[tid] += red[tid + s]; redi[tid] += redi[tid + s]; }
            __syncthreads();
        }
        if (tid == 0) {
            out[LOSS_OFF]  = red[0] / (float)ZQ_ELEMS;
            out[USAGE_OFF] = (float)redi[0] / (float)KCODES;
        }
    }
}

// ---------------------------------------------------------------------------
extern "C" void kernel_launch(void* const* d_in, const int* in_sizes, int n_in,
                              void* d_out, int out_size) {
    const float* ze  = (const float*)d_in[0];
    const float* emb = (const float*)d_in[1];
    float* out = (float*)d_out;

    cudaFuncSetAttribute(vq_main, cudaFuncAttributeMaxDynamicSharedMemorySize,
                         SMEM_BYTES);

    vq_prep<<<8, 128>>>(emb);
    vq_main<<<NBLOCKS, 256, SMEM_BYTES>>>(ze, emb, out);
}

// round 17
// speedup vs baseline: 4.8182x; 4.8182x over previous
#include <cuda_runtime.h>
#include <cuda_bf16.h>
#include <cstdint>

// Shapes fixed by reference setup_inputs():
//   z_e: (B=64, D=64, H=32, W=32) fp32, embedding: (K=1024, D=64) fp32
// Output layout (fp32 concat):
//   [0, 4194304)   z_q (B,D,H,W)
//   [4194304]      commitment_loss
//   [4194305,...)  indices (B,H,W) as float (65536)
//   [4259841]      codebook_usage

#define NVEC   65536
#define DDIM   64
#define KCODES 1024
#define ZQ_ELEMS 4194304
#define LOSS_OFF 4194304
#define IDX_OFF  4194305
#define USAGE_OFF 4259841

#define TAU 0.01f
#define NBLOCKS 512

// ---- dynamic smem byte offsets ----
#define AHI_OFF   0        // A hi fragments: 8 tiles x 2KB            16KB
#define ALO_OFF   16384    // A lo fragments                           16KB
#define BUF0_OFF  32768    // B chunk buffer 0 (64 codes, hi+lo)       16KB
#define BUF1_OFF  49152    // B chunk buffer 1 (also X staging)        16KB
#define CS_OFF    65536    // 1024 x float half-norms                   4KB
#define SIDX_OFF  69632    // 128 x int
#define SFB_OFF   70144    // 128 x int flags
#define SMASK_OFF 70656    // 4 x uint ballot masks
#define XROW_OFF  70672    // 64 x float refinement row
#define WV_OFF    70928    // 8 x float
#define WI_OFF    70960    // 8 x int
#define RED_OFF   70992    // 256 x float
#define SOLD_OFF  72016    // uint
#define SMEM_BYTES 72064   // x3 CTAs = 216KB <= 227KB/SM

// ---- scratch (no device allocation allowed) ----
__device__ float        g_chalf[KCODES];        // 0.5*||e_k||^2
__device__ unsigned int g_b[16 * 4096];         // B image: 16 chunks x 16KB, {hi,lo} interleaved frags
__device__ int          g_used[KCODES];
__device__ float        g_partial[NBLOCKS];
__device__ unsigned int g_done_ctr;

__device__ __forceinline__ uint32_t smem_u32(const void* p) {
    uint32_t a;
    asm("{ .reg .u64 t; cvta.to.shared.u64 t, %1; cvt.u32.u64 %0, t; }" : "=r"(a) : "l"(p));
    return a;
}

#define CP_ASYNC16(dst, src) \
    asm volatile("cp.async.cg.shared.global [%0], [%1], 16;" :: "r"(dst), "l"(src))
#define CP_COMMIT() asm volatile("cp.async.commit_group;" ::: "memory")
#define CP_WAIT1()  asm volatile("cp.async.wait_group 1;" ::: "memory")
#define CP_WAIT0()  asm volatile("cp.async.wait_group 0;" ::: "memory")

__device__ __forceinline__ void mma16816(float* d, const uint4 a, const uint2 b) {
    asm volatile(
        "mma.sync.aligned.m16n8k16.row.col.f32.bf16.bf16.f32 "
        "{%0,%1,%2,%3}, {%4,%5,%6,%7}, {%8,%9}, {%0,%1,%2,%3};"
        : "+f"(d[0]), "+f"(d[1]), "+f"(d[2]), "+f"(d[3])
        : "r"(a.x), "r"(a.y), "r"(a.z), "r"(a.w), "r"(b.x), "r"(b.y));
}

__device__ __forceinline__ void split_bf16(float x, unsigned short& h, unsigned short& l) {
    __nv_bfloat16 bh = __float2bfloat16(x);
    __nv_bfloat16 bl = __float2bfloat16(x - __bfloat162float(bh));
    h = __bfloat16_as_ushort(bh);
    l = __bfloat16_as_ushort(bl);
}

// ---------------------------------------------------------------------------
// Kernel A: half-norms + interleaved {hi,lo} fragment image of B. <<<8,128>>>
// Image: chunk=k/64 (16KB). code c=k%64 owns 256B. dim-pair d2: ks=d2>>3,
// pr=d2&7, p=pr&3, w=(pr&4)>>2. 16B frag at c*256 + ((ks*64+p*16)^((c&1)<<6))
// holds {eh_w0, eh_w1, el_w0, el_w1}.  (identical to the R14 proven image)
// ---------------------------------------------------------------------------
__global__ void vq_prep(const float* __restrict__ emb) {
    int t = blockIdx.x * 128 + threadIdx.x;   // code id 0..1023
    const float* ep = emb + (size_t)t * DDIM;
    char* bimg = (char*)g_b + (t >> 6) * 16384;
    int c = t & 63;
    float s = 0.f;
#pragma unroll
    for (int d2 = 0; d2 < 32; d2++) {
        float x0 = ep[2 * d2], x1 = ep[2 * d2 + 1];
        s = fmaf(x0, x0, s);
        s = fmaf(x1, x1, s);
        unsigned short h0, l0, h1, l1;
        split_bf16(x0, h0, l0);
        split_bf16(x1, h1, l1);
        unsigned uh = (unsigned)h0 | ((unsigned)h1 << 16);
        unsigned ul = (unsigned)l0 | ((unsigned)l1 << 16);
        int ks = d2 >> 3, pr = d2 & 7;
        int X = c * 256 + (((ks * 64) + ((pr & 3) * 16)) ^ ((c & 1) << 6));
        int w = (pr & 4) >> 2;
        *(unsigned*)(bimg + X + w * 4)     = uh;
        *(unsigned*)(bimg + X + 8 + w * 4) = ul;
    }
    g_chalf[t] = 0.5f * s;
    g_used[t] = 0;
    if (t == 0) g_done_ctr = 0u;
}

// ---------------------------------------------------------------------------
// Kernel B: HMMA 3-split distance GEMM + argmax + refinement + epilogue.
// grid = 512 blocks (128 vectors each), 256 threads (8 warps, 1 m16 tile ea).
// Smaller CTA footprint -> 3 CTAs/SM (24 warps) for latency hiding.
// ---------------------------------------------------------------------------
__global__ void __launch_bounds__(256, 3)
vq_main(const float* __restrict__ ze, const float* __restrict__ emb,
        float* __restrict__ out) {
    extern __shared__ char sm[];
    const uint32_t sbase = smem_u32(sm);
    const int tid = threadIdx.x;
    const int wid = tid >> 5;
    const int lid = tid & 31;
    const int g   = lid >> 2;
    const int p   = lid & 3;
    const int n0  = blockIdx.x * 128;
    const int b   = n0 >> 10;
    const int hw0 = n0 & 1023;
    const size_t zbase = (size_t)b * 65536 + hw0;

    float*    csp    = (float*)(sm + CS_OFF);
    int*      sidx   = (int*)(sm + SIDX_OFF);
    int*      sflagb = (int*)(sm + SFB_OFF);
    unsigned* smask  = (unsigned*)(sm + SMASK_OFF);
    float*    xrow   = (float*)(sm + XROW_OFF);
    float*    wv     = (float*)(sm + WV_OFF);
    int*      wi     = (int*)(sm + WI_OFF);
    float*    red    = (float*)(sm + RED_OFF);
    unsigned* sold   = (unsigned*)(sm + SOLD_OFF);

    // ---- prefetch B chunk 0 into BUF0 (X staging uses BUF1) ----
    {
        const uint4* src = (const uint4*)g_b;
#pragma unroll
        for (int j = 0; j < 4; j++)
            CP_ASYNC16(sbase + BUF0_OFF + (tid + j * 256) * 16, src + tid + j * 256);
        CP_COMMIT();
    }

    // ---- half-norms into smem ----
#pragma unroll
    for (int i = 0; i < 4; i++) csp[tid + i * 256] = g_chalf[tid + i * 256];

    // ---- convert X into A hi/lo fragments: 2 passes of 32 dims ----
#pragma unroll
    for (int h = 0; h < 2; h++) {
        float4* Xs4 = (float4*)(sm + BUF1_OFF);   // [32 dims][32 float4]
#pragma unroll
        for (int i = 0; i < 4; i++) {
            int q = tid + i * 256;
            int d = q >> 5, c4 = q & 31;
            Xs4[d * 32 + c4] =
                ((const float4*)(ze + zbase + (size_t)(h * 32 + d) * 1024))[c4];
        }
        __syncthreads();
        const float* Xs = (const float*)(sm + BUF1_OFF);
        const int row = tid & 127;
        const int hh  = tid >> 7;                 // two thread-groups split the 16 d2
        const int tile = row >> 4, r16 = row & 15;
        const int gg = r16 & 7, hi8 = r16 >> 3;
#pragma unroll
        for (int j = 0; j < 8; j++) {
            int d2l = hh * 8 + j;                 // 0..15 within pass
            float x0 = Xs[(2 * d2l) * 128 + row];
            float x1 = Xs[(2 * d2l + 1) * 128 + row];
            unsigned short h0, l0, h1, l1;
            split_bf16(x0, h0, l0);
            split_bf16(x1, h1, l1);
            unsigned uh = (unsigned)h0 | ((unsigned)h1 << 16);
            unsigned ul = (unsigned)l0 | ((unsigned)l1 << 16);
            int ks = h * 2 + (d2l >> 3), pr = d2l & 7;
            int slot = hi8 + ((pr & 4) >> 1);
            int off = tile * 2048 + (ks * 32 + gg * 4 + (pr & 3)) * 16 + slot * 4;
            *(unsigned*)(sm + AHI_OFF + off) = uh;
            *(unsigned*)(sm + ALO_OFF + off) = ul;
        }
        __syncthreads();
    }

    // ---- main loop: 16 chunks of 64 codes, double-buffered via cp.async ----
    float v[2], sec[2];
    int   ix[2];
#pragma unroll
    for (int i = 0; i < 2; i++) { v[i] = -3.4e38f; sec[i] = -3.4e38f; ix[i] = 0; }

    const int abase = wid * 2048;   // warp w owns tile w (rows w*16..w*16+15)

    for (int chunk = 0; chunk < 16; chunk++) {
        if (chunk < 15) {
            const uint4* src = (const uint4*)g_b + (chunk + 1) * 1024;
            uint32_t dst = sbase + (((chunk + 1) & 1) ? BUF1_OFF : BUF0_OFF);
#pragma unroll
            for (int j = 0; j < 4; j++)
                CP_ASYNC16(dst + (tid + j * 256) * 16, src + tid + j * 256);
            CP_COMMIT();
            CP_WAIT1();
        } else {
            CP_WAIT0();
        }
        __syncthreads();

        const char* bbuf = sm + ((chunk & 1) ? BUF1_OFF : BUF0_OFF);

        float acc[8][4];
#pragma unroll
        for (int q = 0; q < 8; q++)
#pragma unroll
            for (int j = 0; j < 4; j++) acc[q][j] = 0.f;

#pragma unroll
        for (int ks = 0; ks < 4; ks++) {
            uint4 ah = *(const uint4*)(sm + AHI_OFF + abase + (ks * 32 + lid) * 16);
            uint4 al = *(const uint4*)(sm + ALO_OFF + abase + (ks * 32 + lid) * 16);
#pragma unroll
            for (int nt = 0; nt < 8; nt++) {
                int c = nt * 8 + g;
                uint4 bf = *(const uint4*)(bbuf + c * 256 +
                           ((ks * 64 + p * 16) ^ ((c & 1) << 6)));
                uint2 bh = make_uint2(bf.x, bf.y);
                uint2 bl = make_uint2(bf.z, bf.w);
                mma16816(acc[nt], ah, bh);
                mma16816(acc[nt], al, bh);
                mma16816(acc[nt], ah, bl);
            }
        }

        // fold: s = dot - 0.5||e||^2 ; rows wid*16+g (d0,d1), wid*16+8+g (d2,d3)
#pragma unroll
        for (int nt = 0; nt < 8; nt++) {
            int kk = chunk * 64 + nt * 8 + 2 * p;
            float2 ch = *(const float2*)(csp + kk);
            float s0 = acc[nt][0] - ch.x, s1 = acc[nt][1] - ch.y;
            float s2 = acc[nt][2] - ch.x, s3 = acc[nt][3] - ch.y;
            if (s0 > v[0]) { sec[0] = v[0]; v[0] = s0; ix[0] = kk; }     else sec[0] = fmaxf(sec[0], s0);
            if (s1 > v[0]) { sec[0] = v[0]; v[0] = s1; ix[0] = kk + 1; } else sec[0] = fmaxf(sec[0], s1);
            if (s2 > v[1]) { sec[1] = v[1]; v[1] = s2; ix[1] = kk; }     else sec[1] = fmaxf(sec[1], s2);
            if (s3 > v[1]) { sec[1] = v[1]; v[1] = s3; ix[1] = kk + 1; } else sec[1] = fmaxf(sec[1], s3);
        }
        __syncthreads();
    }

    // ---- top-2 merge across the 4 lanes (p) sharing each row ----
#pragma unroll
    for (int i = 0; i < 2; i++) {
#pragma unroll
        for (int off = 1; off <= 2; off <<= 1) {
            float ov = __shfl_xor_sync(0xffffffffu, v[i], off);
            int   oi = __shfl_xor_sync(0xffffffffu, ix[i], off);
            float os = __shfl_xor_sync(0xffffffffu, sec[i], off);
            float mn = fminf(v[i], ov);
            sec[i] = fmaxf(mn, fmaxf(sec[i], os));
            ix[i] = (ov > v[i]) ? oi : ((ov < v[i]) ? ix[i] : min(ix[i], oi));
            v[i] = fmaxf(v[i], ov);
        }
    }
    if (p == 0) {
        int rA = wid * 16 + g, rB = rA + 8;
        sidx[rA] = ix[0]; sflagb[rA] = (v[0] - sec[0] < TAU) ? 1 : 0;
        sidx[rB] = ix[1]; sflagb[rB] = (v[1] - sec[1] < TAU) ? 1 : 0;
    }
    __syncthreads();

    // ---- ballot masks for rows 0..127 ----
    {
        int fl = (tid < 128) ? sflagb[tid] : 0;
        unsigned bm = __ballot_sync(0xffffffffu, fl != 0);
        if (lid == 0 && wid < 4) smask[wid] = bm;
    }
    __syncthreads();

    // ---- exact fp32 refinement for flagged rows (~0.4% with 3-split) ----
    for (int w = 0; w < 4; w++) {
        unsigned m = smask[w];
        while (m) {
            int nl = w * 32 + (__ffs(m) - 1);
            m &= m - 1;
            if (tid < 64) xrow[tid] = ze[zbase + (size_t)tid * 1024 + nl];
            __syncthreads();
            float bl = -3.4e38f; int bi = 0;
#pragma unroll
            for (int j = 0; j < 4; j++) {
                int k = tid * 4 + j;
                const float4* er = (const float4*)(emb + (size_t)k * DDIM);
                float dot = 0.f;
#pragma unroll
                for (int q4 = 0; q4 < 16; q4++) {
                    float4 ev = er[q4];
                    float4 xv = *(const float4*)&xrow[q4 * 4];
                    dot = fmaf(xv.x, ev.x, dot);
                    dot = fmaf(xv.y, ev.y, dot);
                    dot = fmaf(xv.z, ev.z, dot);
                    dot = fmaf(xv.w, ev.w, dot);
                }
                float s = dot - csp[k];
                if (s > bl) { bl = s; bi = k; }
            }
#pragma unroll
            for (int off = 16; off; off >>= 1) {
                float ov = __shfl_xor_sync(0xffffffffu, bl, off);
                int   oi = __shfl_xor_sync(0xffffffffu, bi, off);
                if (ov > bl || (ov == bl && oi < bi)) { bl = ov; bi = oi; }
            }
            if (lid == 0) { wv[wid] = bl; wi[wid] = bi; }
            __syncthreads();
            if (tid == 0) {
                float fb = wv[0]; int fi = wi[0];
#pragma unroll
                for (int ww = 1; ww < 8; ww++)
                    if (wv[ww] > fb || (wv[ww] == fb && wi[ww] < fi)) { fb = wv[ww]; fi = wi[ww]; }
                sidx[nl] = fi;
            }
            __syncthreads();
        }
    }

    // ---- epilogue: 2 threads per row (half = dims 0..31 / 32..63) ----
    {
        const int row  = tid & 127;
        const int half = tid >> 7;
        const int k = sidx[row];
        if (half == 0) {
            out[IDX_OFF + n0 + row] = (float)k;
            g_used[k] = 1;
        }
        const float* ep = emb + (size_t)k * DDIM + half * 32;
        float lsum = 0.f;
#pragma unroll
        for (int d = 0; d < 32; d++) {
            float e = __ldg(ep + d);                                   // codebook: L1/L2 hit
            float x = ze[zbase + (size_t)(half * 32 + d) * 1024 + row]; // coalesced
            float df = x - e;
            lsum = fmaf(df, df, lsum);
            out[zbase + (size_t)(half * 32 + d) * 1024 + row] = e;     // coalesced
        }
        red[tid] = lsum;
    }
    __syncthreads();
#pragma unroll
    for (int s = 128; s; s >>= 1) {
        if (tid < s) red[tid] += red[tid + s];
        __syncthreads();
    }
    if (tid == 0) g_partial[blockIdx.x] = red[0];

    // ---- last-block final reductions ----
    __threadfence();
    __syncthreads();
    if (tid == 0) *sold = atomicAdd(&g_done_ctr, 1u);
    __syncthreads();
    if (*sold == NBLOCKS - 1) {
        __threadfence();
        volatile float* gp = g_partial;
        volatile int*   gu = g_used;
        float ls = gp[tid] + gp[tid + 256];
        int us = 0;
#pragma unroll
        for (int j = 0; j < 4; j++) us += gu[tid * 4 + j];
        int* redi = (int*)(sm + AHI_OFF);   // dead region
        red[tid]  = ls;
        redi[tid] = us;
        __syncthreads();
#pragma unroll
        for (int s = 128; s; s >>= 1) {
            if (tid < s) { red[tid] += red[tid + s]; redi[tid] += redi[tid + s]; }
            __syncthreads();
        }
        if (tid == 0) {
            out[LOSS_OFF]  = red[0] / (float)ZQ_ELEMS;
            out[USAGE_OFF] = (float)redi[0] / (float)KCODES;
        }
    }
}

// ---------------------------------------------------------------------------
extern "C" void kernel_launch(void* const* d_in, const int* in_sizes, int n_in,
                              void* d_out, int out_size) {
    const float* ze  = (const float*)d_in[0];
    const float* emb = (const float*)d_in[1];
    float* out = (float*)d_out;

    cudaFuncSetAttribute(vq_main, cudaFuncAttributeMaxDynamicSharedMemorySize,
                         SMEM_BYTES);

    vq_prep<<<8, 128>>>(emb);
    vq_main<<<NBLOCKS, 256, SMEM_BYTES>>>(ze, emb, out);
}